// round 7
// baseline (speedup 1.0000x reference)
#include <cuda_runtime.h>
#include <math.h>

// dag[i,j] closed form (reference scan collapses; ST forward == hard sample):
//   b[i,j]  = (e + g0) > (1 - e + g1)
//   nr[j]   = !((rp[j] + gr0[j]) > (1 - rp[j] + gr1[j]))
//   dag[i,j] = 0                               (i == j)
//            = b[i,j]*nr[j]                    (j > i)
//            = b[i,j]*nr[j]*(1 - b[j,i]*nr[i]) (j < i)
//
// TILE=32 tile pairs, triangular grid (2080 blocks for n=2048).
// 512-thread role-split blocks: threads [0,256) own upper tile P(bi,bj),
// threads [256,512) own lower tile Q(bj,bi). One float4 group per thread,
// all loads issued at block start -> one DRAM round per block.

#define TILE 32

__device__ __forceinline__ int tri_row(int bid, int T) {
    double d = (2.0 * T + 1.0);
    int bi = (int)floor((d - sqrt(d * d - 8.0 * (double)bid)) * 0.5);
    if (bi < 0) bi = 0;
    if (bi > T - 1) bi = T - 1;
    if ((bi + 1) * T - ((bi + 1) * bi) / 2 <= bid) bi++;
    else if (bi * T - (bi * (bi - 1)) / 2 > bid) bi--;
    return bi;
}

__global__ __launch_bounds__(512) void dag_pair_kernel(
    const float*  __restrict__ rootp,   // (n)
    const float4* __restrict__ edgep4,  // (n, n/4)
    const float2* __restrict__ groot,   // (n) float2
    const float4* __restrict__ gedge4,  // (n, n/2) float4 = 2 cols
    float4*       __restrict__ out4,    // (n, n/4)
    int n, int T)                        // T = n/TILE
{
    const int bid = blockIdx.x;
    const int bi  = tri_row(bid, T);
    const int bj  = bi + (bid - (bi * T - (bi * (bi - 1)) / 2));

    const int tid  = threadIdx.x;
    const int half = tid >> 8;          // 0 = P role, 1 = Q role
    const int t    = tid & 255;
    const int lr   = t >> 3;            // 0..31 local row
    const int cg   = t & 7;             // 0..7 float4 col group
    const int c4   = cg << 2;           // 0,4,...,28
    const bool diag = (bi == bj);
    const bool qact = (half == 1) && !diag;   // Q role active?

    const int n4 = n >> 2;
    const int n2 = n >> 1;

    __shared__ float vP[TILE][TILE + 1];
    __shared__ float nrs[2][TILE];      // nrs[0] = nrI (bi tile), nrs[1] = nrJ (bj tile)

    // Root loads (tiny, L2-resident) issued first.
    if (tid < 2 * TILE) {
        int local = tid & (TILE - 1);
        int base  = (tid < TILE) ? bi : bj;
        int g     = base * TILE + local;
        float p   = rootp[g];
        float2 gr = groot[g];
        nrs[tid >> 5][local] = ((p + gr.x) > (1.0f - p + gr.y)) ? 0.0f : 1.0f;
    }

    // Tile loads: one float4 group per thread, both tiles concurrently.
    const int rowT = (half ? bj : bi) * TILE + lr;
    const int colg = (half ? bi : bj) * 8 + cg;
    float4 e  = make_float4(0.f, 0.f, 0.f, 0.f);
    float4 g0 = make_float4(0.f, 0.f, 0.f, 0.f);
    float4 g1 = make_float4(0.f, 0.f, 0.f, 0.f);
    if (half == 0 || qact) {
        e = edgep4[(long)rowT * n4 + colg];
        long gi = (long)rowT * n2 + (colg << 1);
        g0 = gedge4[gi];
        g1 = gedge4[gi + 1];
    }

    __syncthreads();   // nrs ready

    float v0 = 0.f, v1 = 0.f, v2 = 0.f, v3 = 0.f;
    if (half == 0) {
        // P role: v = b * nrJ[col]
        v0 = (((e.x + g0.x) > (1.0f - e.x + g0.y)) ? 1.0f : 0.0f) * nrs[1][c4 + 0];
        v1 = (((e.y + g0.z) > (1.0f - e.y + g0.w)) ? 1.0f : 0.0f) * nrs[1][c4 + 1];
        v2 = (((e.z + g1.x) > (1.0f - e.z + g1.y)) ? 1.0f : 0.0f) * nrs[1][c4 + 2];
        v3 = (((e.w + g1.z) > (1.0f - e.w + g1.w)) ? 1.0f : 0.0f) * nrs[1][c4 + 3];
        vP[lr][c4 + 0] = v0;
        vP[lr][c4 + 1] = v1;
        vP[lr][c4 + 2] = v2;
        vP[lr][c4 + 3] = v3;
        if (!diag)
            out4[(long)rowT * n4 + colg] = make_float4(v0, v1, v2, v3);
    } else if (qact) {
        // Q role: q = b * nrI[col] (independent of vP; compute before barrier)
        v0 = (((e.x + g0.x) > (1.0f - e.x + g0.y)) ? 1.0f : 0.0f) * nrs[0][c4 + 0];
        v1 = (((e.y + g0.z) > (1.0f - e.y + g0.w)) ? 1.0f : 0.0f) * nrs[0][c4 + 1];
        v2 = (((e.z + g1.x) > (1.0f - e.z + g1.y)) ? 1.0f : 0.0f) * nrs[0][c4 + 2];
        v3 = (((e.w + g1.z) > (1.0f - e.w + g1.w)) ? 1.0f : 0.0f) * nrs[0][c4 + 3];
    }

    __syncthreads();   // vP fully written

    if (qact) {
        // dag_Q = q * (1 - vP^T); conflict-free via +1 pad
        float o0 = v0 * (1.0f - vP[c4 + 0][lr]);
        float o1 = v1 * (1.0f - vP[c4 + 1][lr]);
        float o2 = v2 * (1.0f - vP[c4 + 2][lr]);
        float o3 = v3 * (1.0f - vP[c4 + 3][lr]);
        out4[(long)rowT * n4 + colg] = make_float4(o0, o1, o2, o3);
    } else if (half == 0 && diag) {
        // Diagonal tile: both triangles + zero diagonal.
        float o[4] = {v0, v1, v2, v3};
        #pragma unroll
        for (int k = 0; k < 4; k++) {
            int cc = c4 + k;
            if (cc < lr)       o[k] = o[k] * (1.0f - vP[cc][lr]);
            else if (cc == lr) o[k] = 0.0f;
        }
        out4[(long)rowT * n4 + colg] = make_float4(o[0], o[1], o[2], o[3]);
    }
}

extern "C" void kernel_launch(void* const* d_in, const int* in_sizes, int n_in,
                              void* d_out, int out_size) {
    const float*  rootp  = (const float*)d_in[0];
    const float4* edgep4 = (const float4*)d_in[1];
    const float2* groot  = (const float2*)d_in[2];
    const float4* gedge4 = (const float4*)d_in[3];
    float4* out = (float4*)d_out;
    int n = in_sizes[0];
    int T = n / TILE;
    int nblk = T * (T + 1) / 2;

    dag_pair_kernel<<<nblk, 512>>>(rootp, edgep4, groot, gedge4, out, n, T);
}